// round 13
// baseline (speedup 1.0000x reference)
#include <cuda_runtime.h>
#include <cuda_fp16.h>
#include <cstdint>
#include <cstddef>

// ---- problem dims ----
#define BDIM 1024
#define VDIM 50000
#define DDIM 300
#define NPAD_OUT 320
#define MTILE 128
#define NTILE 160
#define KT 32
#define NSPLIT 9
#define NCH 174               // 9*174*32 = 50112 >= 50000 (guarded tail)

// SMEM (fp16): A 128 rows x 32 halves, row padded to 80 B; B 32 rows x 160 halves, padded to 336 B
#define A_ROW_B 80
#define B_ROW_B 336
#define A_TILE_B (MTILE * A_ROW_B)        // 10240
#define B_TILE_B (KT * B_ROW_B)           // 10752
#define STAGE_B (A_TILE_B + B_TILE_B)     // 20992
// double buffered: 41984 B static shared

__device__ float g_partial[NSPLIT * BDIM * NPAD_OUT];   // ~11.8 MB

// ---------------- helpers ----------------
__device__ __forceinline__ uint32_t smem_u32(const void* p) {
    uint32_t a;
    asm("{ .reg .u64 t; cvta.to.shared.u64 t, %1; cvt.u32.u64 %0, t; }" : "=r"(a) : "l"(p));
    return a;
}
__device__ __forceinline__ void ldmx4(uint32_t* r, uint32_t addr) {
    asm volatile("ldmatrix.sync.aligned.m8n8.x4.shared.b16 {%0,%1,%2,%3}, [%4];"
                 : "=r"(r[0]), "=r"(r[1]), "=r"(r[2]), "=r"(r[3]) : "r"(addr));
}
__device__ __forceinline__ void ldmx4t(uint32_t* r, uint32_t addr) {
    asm volatile("ldmatrix.sync.aligned.m8n8.x4.trans.shared.b16 {%0,%1,%2,%3}, [%4];"
                 : "=r"(r[0]), "=r"(r[1]), "=r"(r[2]), "=r"(r[3]) : "r"(addr));
}
__device__ __forceinline__ void mma16(float* c, const uint32_t* a, uint32_t b0, uint32_t b1) {
    asm volatile(
        "mma.sync.aligned.m16n8k16.row.col.f32.f16.f16.f32 "
        "{%0,%1,%2,%3}, {%4,%5,%6,%7}, {%8,%9}, {%0,%1,%2,%3};"
        : "+f"(c[0]), "+f"(c[1]), "+f"(c[2]), "+f"(c[3])
        : "r"(a[0]), "r"(a[1]), "r"(a[2]), "r"(a[3]), "r"(b0), "r"(b1));
}
__device__ __forceinline__ uint32_t h2u(__half2 h) {
    union { __half2 h; uint32_t u; } c; c.h = h; return c.u;
}

// ---------------- GEMM (fp16 MMA, fused fp32->fp16 convert, single barrier/iter) ----------------
__global__ void __launch_bounds__(256, 1)
gemm_kernel(const float* __restrict__ A, const float* __restrict__ W) {
    __shared__ __align__(128) unsigned char smem[2 * STAGE_B];
    const uint32_t sbase = smem_u32(smem);
    const int tid = threadIdx.x, w = tid >> 5, lane = tid & 31;
    const int wm = w & 3, wn = w >> 2;            // warp grid 4(M) x 2(N)
    const int mt = blockIdx.x;                    // 0..7
    const int nt = blockIdx.y;                    // 0..1
    const int ks = blockIdx.z;                    // 0..8
    const int nbase = nt * NTILE;
    const int c0 = ks * NCH;

    // ---- LDG assignments (fixed per thread) ----
    const int arow = tid >> 3, aq = tid & 7;      // A: rows arow+32i, float4 #aq
    const float* aptr[4];
#pragma unroll
    for (int i = 0; i < 4; i++)
        aptr[i] = A + (size_t)(mt * MTILE + arow + 32 * i) * VDIM + aq * 4;

    int bro[5]; const float* bptr[5]; bool bok[5]; uint32_t b_sts[5];
#pragma unroll
    for (int i = 0; i < 5; i++) {
        int idx = tid + 256 * i;
        int r = idx / 40, q = idx - 40 * r;       // B: k-row r, float4 #q
        bro[i] = r;
        bok[i] = (nbase + q * 4) < DDIM;          // 300 % 4 == 0: full or none
        bptr[i] = W + (size_t)r * DDIM + nbase + q * 4;
        b_sts[i] = (uint32_t)(A_TILE_B + r * B_ROW_B + q * 8);
    }
    const uint32_t a_sts = (uint32_t)(arow * A_ROW_B + aq * 8);

    // ---- ldmatrix per-lane base offsets ----
    const int al = lane & 15, ak = lane >> 4;
    const uint32_t a_lm = (uint32_t)((wm * 32 + al) * A_ROW_B + ak * 16);
    const int bl = lane & 7, bk8 = (lane >> 3) & 1, bn8 = lane >> 4;
    const uint32_t b_lm = (uint32_t)(A_TILE_B + (bk8 * 8 + bl) * B_ROW_B
                                     + (wn * 80 + bn8 * 8) * 2);

    float4 sa[4], sb[5];      // staging registers (one chunk ahead of SMEM)

    float acc[2][10][4];
#pragma unroll
    for (int t = 0; t < 2; t++)
#pragma unroll
        for (int j = 0; j < 10; j++)
#pragma unroll
            for (int e = 0; e < 4; e++) acc[t][j][e] = 0.0f;

    // ---- ldg / sts helpers ----
    auto ldg_chunk = [&](int chunk) {
        const int kb = chunk * KT;
        const bool aok = (kb + aq * 4 + 4) <= VDIM;   // VDIM % 4 == 0
#pragma unroll
        for (int i = 0; i < 4; i++)
            sa[i] = aok ? *reinterpret_cast<const float4*>(aptr[i] + kb)
                        : make_float4(0.f, 0.f, 0.f, 0.f);
#pragma unroll
        for (int i = 0; i < 5; i++) {
            bool ok = bok[i] && (kb + bro[i]) < VDIM;
            sb[i] = ok ? *reinterpret_cast<const float4*>(bptr[i] + (size_t)kb * DDIM)
                       : make_float4(0.f, 0.f, 0.f, 0.f);
        }
    };
    auto sts_chunk = [&](uint32_t bufoff) {
        unsigned char* base = smem + bufoff;
#pragma unroll
        for (int i = 0; i < 4; i++) {
            uint32_t u0 = h2u(__floats2half2_rn(sa[i].x, sa[i].y));
            uint32_t u1 = h2u(__floats2half2_rn(sa[i].z, sa[i].w));
            *reinterpret_cast<uint2*>(base + a_sts + i * 32 * A_ROW_B) = make_uint2(u0, u1);
        }
#pragma unroll
        for (int i = 0; i < 5; i++) {
            uint32_t u0 = h2u(__floats2half2_rn(sb[i].x, sb[i].y));
            uint32_t u1 = h2u(__floats2half2_rn(sb[i].z, sb[i].w));
            *reinterpret_cast<uint2*>(base + b_sts[i]) = make_uint2(u0, u1);
        }
    };

    // ---- prologue: chunk 0 -> buf0 (smem), chunk 1 -> regs ----
    ldg_chunk(c0);
    sts_chunk(0);
    if (1 < NCH) ldg_chunk(c0 + 1);
    __syncthreads();

    // ---- mainloop: ONE barrier per iteration ----
    // Hazard audit: sts at iter i targets buf (i+1)&1, whose last readers (iter i-1)
    // were ordered by the end-of-(i-1) barrier. MMAs of iter i read buf i&1 — disjoint.
    for (int i = 0; i < NCH; i++) {
        const uint32_t buf = (uint32_t)((i & 1) * STAGE_B);
        const uint32_t aa = sbase + buf + a_lm;
        const uint32_t bb = sbase + buf + b_lm;

        // kstep 0
        {
            uint32_t af0[4], af1[4];
            ldmx4(af0, aa);
            ldmx4(af1, aa + 16 * A_ROW_B);
#pragma unroll
            for (int jp = 0; jp < 5; jp++) {
                uint32_t bf[4];
                ldmx4t(bf, bb + jp * 32);
                mma16(acc[0][2 * jp],     af0, bf[0], bf[1]);
                mma16(acc[1][2 * jp],     af1, bf[0], bf[1]);
                mma16(acc[0][2 * jp + 1], af0, bf[2], bf[3]);
                mma16(acc[1][2 * jp + 1], af1, bf[2], bf[3]);
            }
        }

        // stage next chunk into the other buffer (overlaps with MMA pipe),
        // then start the chunk-after-next global loads
        if (i + 1 < NCH) sts_chunk((uint32_t)(((i + 1) & 1) * STAGE_B));
        if (i + 2 < NCH) ldg_chunk(c0 + i + 2);

        // kstep 1
        {
            uint32_t af0[4], af1[4];
            ldmx4(af0, aa + 32);
            ldmx4(af1, aa + 16 * A_ROW_B + 32);
#pragma unroll
            for (int jp = 0; jp < 5; jp++) {
                uint32_t bf[4];
                ldmx4t(bf, bb + 16 * B_ROW_B + jp * 32);
                mma16(acc[0][2 * jp],     af0, bf[0], bf[1]);
                mma16(acc[1][2 * jp],     af1, bf[0], bf[1]);
                mma16(acc[0][2 * jp + 1], af0, bf[2], bf[3]);
                mma16(acc[1][2 * jp + 1], af1, bf[2], bf[3]);
            }
        }
        __syncthreads();
    }

    // ---- epilogue: write split-K partials ----
    const int lrow = lane >> 2, lcol = lane & 3;
#pragma unroll
    for (int t = 0; t < 2; t++) {
        int row0 = mt * MTILE + wm * 32 + t * 16 + lrow;
#pragma unroll
        for (int j = 0; j < 10; j++) {
            int col = nbase + wn * 80 + j * 8 + 2 * lcol;
            float* p0 = g_partial + ((size_t)ks * BDIM + row0) * NPAD_OUT + col;
            float* p1 = g_partial + ((size_t)ks * BDIM + row0 + 8) * NPAD_OUT + col;
            *reinterpret_cast<float2*>(p0) = make_float2(acc[t][j][0], acc[t][j][1]);
            *reinterpret_cast<float2*>(p1) = make_float2(acc[t][j][2], acc[t][j][3]);
        }
    }
}

// ---------------- reduce + L2 normalize ----------------
__global__ void __launch_bounds__(320) reduce_norm_kernel(float* __restrict__ out) {
    const int row = blockIdx.x;
    const int d = threadIdx.x;
    __shared__ float ssum[10];
    __shared__ float sinv;
    float a = 0.0f;
    if (d < DDIM) {
#pragma unroll
        for (int s = 0; s < NSPLIT; s++)
            a += g_partial[((size_t)s * BDIM + row) * NPAD_OUT + d];
    }
    float sq = a * a;
#pragma unroll
    for (int off = 16; off > 0; off >>= 1)
        sq += __shfl_xor_sync(0xFFFFFFFFu, sq, off);
    if ((threadIdx.x & 31) == 0) ssum[threadIdx.x >> 5] = sq;
    __syncthreads();
    if (threadIdx.x == 0) {
        float t = 0.0f;
#pragma unroll
        for (int i = 0; i < 10; i++) t += ssum[i];
        sinv = 1.0f / (sqrtf(t) + 1e-7f);
    }
    __syncthreads();
    if (d < DDIM)
        out[(size_t)row * DDIM + d] = a * sinv;
}

// ---------------- launch ----------------
extern "C" void kernel_launch(void* const* d_in, const int* in_sizes, int n_in,
                              void* d_out, int out_size) {
    const float* labels = (const float*)d_in[0];
    const float* weight = (const float*)d_in[1];
    if (n_in >= 2 && in_sizes[0] == VDIM * DDIM) {   // defensive: identify by size
        labels = (const float*)d_in[1];
        weight = (const float*)d_in[0];
    }
    float* out = (float*)d_out;

    gemm_kernel<<<dim3(BDIM / MTILE, 2, NSPLIT), 256>>>(labels, weight);
    reduce_norm_kernel<<<BDIM, 320>>>(out);
}

// round 14
// speedup vs baseline: 1.3636x; 1.3636x over previous
#include <cuda_runtime.h>
#include <cuda_fp16.h>
#include <cstdint>
#include <cstddef>

// ---- problem dims ----
#define BDIM 1024
#define VDIM 50000
#define DDIM 300
#define NPAD_OUT 320
#define MTILE 128
#define NTILE 160
#define KT 32
#define NSPLIT 9
#define NCH 174               // 9*174*32 = 50112 >= 50000 (guarded tail)

// SMEM (fp16): A 128 rows x 32 halves, row padded to 80 B; B 32 rows x 160 halves, padded to 336 B
#define A_ROW_B 80
#define B_ROW_B 336
#define A_TILE_B (MTILE * A_ROW_B)        // 10240
#define B_TILE_B (KT * B_ROW_B)           // 10752
#define STAGE_B (A_TILE_B + B_TILE_B)     // 20992
// double buffered: 41984 B static shared

__device__ float g_partial[NSPLIT * BDIM * NPAD_OUT];   // ~11.8 MB

// ---------------- helpers ----------------
__device__ __forceinline__ uint32_t smem_u32(const void* p) {
    uint32_t a;
    asm("{ .reg .u64 t; cvta.to.shared.u64 t, %1; cvt.u32.u64 %0, t; }" : "=r"(a) : "l"(p));
    return a;
}
__device__ __forceinline__ void ldmx4(uint32_t* r, uint32_t addr) {
    asm volatile("ldmatrix.sync.aligned.m8n8.x4.shared.b16 {%0,%1,%2,%3}, [%4];"
                 : "=r"(r[0]), "=r"(r[1]), "=r"(r[2]), "=r"(r[3]) : "r"(addr));
}
__device__ __forceinline__ void ldmx4t(uint32_t* r, uint32_t addr) {
    asm volatile("ldmatrix.sync.aligned.m8n8.x4.trans.shared.b16 {%0,%1,%2,%3}, [%4];"
                 : "=r"(r[0]), "=r"(r[1]), "=r"(r[2]), "=r"(r[3]) : "r"(addr));
}
__device__ __forceinline__ void mma16(float* c, const uint32_t* a, uint32_t b0, uint32_t b1) {
    asm volatile(
        "mma.sync.aligned.m16n8k16.row.col.f32.f16.f16.f32 "
        "{%0,%1,%2,%3}, {%4,%5,%6,%7}, {%8,%9}, {%0,%1,%2,%3};"
        : "+f"(c[0]), "+f"(c[1]), "+f"(c[2]), "+f"(c[3])
        : "r"(a[0]), "r"(a[1]), "r"(a[2]), "r"(a[3]), "r"(b0), "r"(b1));
}
__device__ __forceinline__ uint32_t h2u(__half2 h) {
    union { __half2 h; uint32_t u; } c; c.h = h; return c.u;
}

// ---------------- GEMM (fp16 MMA, fused convert, single barrier, STS out of LDSM path) ---------
__global__ void __launch_bounds__(256, 1)
gemm_kernel(const float* __restrict__ A, const float* __restrict__ W) {
    __shared__ __align__(128) unsigned char smem[2 * STAGE_B];
    const uint32_t sbase = smem_u32(smem);
    const int tid = threadIdx.x, w = tid >> 5, lane = tid & 31;
    const int wm = w & 3, wn = w >> 2;            // warp grid 4(M) x 2(N)
    const int mt = blockIdx.x;                    // 0..7
    const int nt = blockIdx.y;                    // 0..1
    const int ks = blockIdx.z;                    // 0..8
    const int nbase = nt * NTILE;
    const int c0 = ks * NCH;

    // ---- LDG assignments (fixed per thread) ----
    const int arow = tid >> 3, aq = tid & 7;      // A: rows arow+32i, float4 #aq
    const float* aptr[4];
#pragma unroll
    for (int i = 0; i < 4; i++)
        aptr[i] = A + (size_t)(mt * MTILE + arow + 32 * i) * VDIM + aq * 4;

    int bro[5]; const float* bptr[5]; bool bok[5]; uint32_t b_sts[5];
#pragma unroll
    for (int i = 0; i < 5; i++) {
        int idx = tid + 256 * i;
        int r = idx / 40, q = idx - 40 * r;       // B: k-row r, float4 #q
        bro[i] = r;
        bok[i] = (nbase + q * 4) < DDIM;          // 300 % 4 == 0: full or none
        bptr[i] = W + (size_t)r * DDIM + nbase + q * 4;
        b_sts[i] = (uint32_t)(A_TILE_B + r * B_ROW_B + q * 8);
    }
    const uint32_t a_sts = (uint32_t)(arow * A_ROW_B + aq * 8);

    // ---- ldmatrix per-lane base offsets ----
    const int al = lane & 15, ak = lane >> 4;
    const uint32_t a_lm = (uint32_t)((wm * 32 + al) * A_ROW_B + ak * 16);
    const int bl = lane & 7, bk8 = (lane >> 3) & 1, bn8 = lane >> 4;
    const uint32_t b_lm = (uint32_t)(A_TILE_B + (bk8 * 8 + bl) * B_ROW_B
                                     + (wn * 80 + bn8 * 8) * 2);

    float4 sa[4], sb[5];      // staging registers (one chunk ahead of SMEM)

    float acc[2][10][4];
#pragma unroll
    for (int t = 0; t < 2; t++)
#pragma unroll
        for (int j = 0; j < 10; j++)
#pragma unroll
            for (int e = 0; e < 4; e++) acc[t][j][e] = 0.0f;

    // ---- ldg / sts helpers ----
    auto ldg_chunk = [&](int chunk) {
        const int kb = chunk * KT;
        const bool aok = (kb + aq * 4 + 4) <= VDIM;   // VDIM % 4 == 0
#pragma unroll
        for (int i = 0; i < 4; i++)
            sa[i] = aok ? *reinterpret_cast<const float4*>(aptr[i] + kb)
                        : make_float4(0.f, 0.f, 0.f, 0.f);
#pragma unroll
        for (int i = 0; i < 5; i++) {
            bool ok = bok[i] && (kb + bro[i]) < VDIM;
            sb[i] = ok ? *reinterpret_cast<const float4*>(bptr[i] + (size_t)kb * DDIM)
                       : make_float4(0.f, 0.f, 0.f, 0.f);
        }
    };
    auto sts_chunk = [&](uint32_t bufoff) {
        unsigned char* base = smem + bufoff;
#pragma unroll
        for (int i = 0; i < 4; i++) {
            uint32_t u0 = h2u(__floats2half2_rn(sa[i].x, sa[i].y));
            uint32_t u1 = h2u(__floats2half2_rn(sa[i].z, sa[i].w));
            *reinterpret_cast<uint2*>(base + a_sts + i * 32 * A_ROW_B) = make_uint2(u0, u1);
        }
#pragma unroll
        for (int i = 0; i < 5; i++) {
            uint32_t u0 = h2u(__floats2half2_rn(sb[i].x, sb[i].y));
            uint32_t u1 = h2u(__floats2half2_rn(sb[i].z, sb[i].w));
            *reinterpret_cast<uint2*>(base + b_sts[i]) = make_uint2(u0, u1);
        }
    };

    // ---- prologue: chunk 0 -> buf0 (smem), chunk 1 -> regs ----
    ldg_chunk(c0);
    sts_chunk(0);
    if (1 < NCH) ldg_chunk(c0 + 1);
    __syncthreads();

    // ---- mainloop: one barrier per iteration; ALL kstep1 LDSMs issue BEFORE the STS block ----
    // Hazard audit (unchanged): sts at iter i targets buf (i+1)&1, last read in iter i-1 and
    // ordered by that iteration's end barrier. All iter-i LDSMs (both ksteps) read buf i&1.
    for (int i = 0; i < NCH; i++) {
        const uint32_t buf = (uint32_t)((i & 1) * STAGE_B);
        const uint32_t aa = sbase + buf + a_lm;
        const uint32_t bb = sbase + buf + b_lm;

        // kstep 0: streaming LDSM + MMA
        {
            uint32_t af0[4], af1[4];
            ldmx4(af0, aa);
            ldmx4(af1, aa + 16 * A_ROW_B);
#pragma unroll
            for (int jp = 0; jp < 5; jp++) {
                uint32_t bf[4];
                ldmx4t(bf, bb + jp * 32);
                mma16(acc[0][2 * jp],     af0, bf[0], bf[1]);
                mma16(acc[1][2 * jp],     af1, bf[0], bf[1]);
                mma16(acc[0][2 * jp + 1], af0, bf[2], bf[3]);
                mma16(acc[1][2 * jp + 1], af1, bf[2], bf[3]);
            }
        }

        // kstep 1: prefetch ALL fragments first (so the STS below can't order-block them)
        uint32_t cf0[4], cf1[4], cbf[5][4];
        ldmx4(cf0, aa + 32);
        ldmx4(cf1, aa + 16 * A_ROW_B + 32);
#pragma unroll
        for (int jp = 0; jp < 5; jp++)
            ldmx4t(cbf[jp], bb + 16 * B_ROW_B + jp * 32);

        // stage next chunk into the other buffer; STS drains under the MMA stream below
        if (i + 1 < NCH) sts_chunk((uint32_t)(((i + 1) & 1) * STAGE_B));
        if (i + 2 < NCH) ldg_chunk(c0 + i + 2);

        // kstep 1 MMAs (register-only deps; independent of the STS above)
#pragma unroll
        for (int jp = 0; jp < 5; jp++) {
            mma16(acc[0][2 * jp],     cf0, cbf[jp][0], cbf[jp][1]);
            mma16(acc[1][2 * jp],     cf1, cbf[jp][0], cbf[jp][1]);
            mma16(acc[0][2 * jp + 1], cf0, cbf[jp][2], cbf[jp][3]);
            mma16(acc[1][2 * jp + 1], cf1, cbf[jp][2], cbf[jp][3]);
        }
        __syncthreads();
    }

    // ---- epilogue: write split-K partials ----
    const int lrow = lane >> 2, lcol = lane & 3;
#pragma unroll
    for (int t = 0; t < 2; t++) {
        int row0 = mt * MTILE + wm * 32 + t * 16 + lrow;
#pragma unroll
        for (int j = 0; j < 10; j++) {
            int col = nbase + wn * 80 + j * 8 + 2 * lcol;
            float* p0 = g_partial + ((size_t)ks * BDIM + row0) * NPAD_OUT + col;
            float* p1 = g_partial + ((size_t)ks * BDIM + row0 + 8) * NPAD_OUT + col;
            *reinterpret_cast<float2*>(p0) = make_float2(acc[t][j][0], acc[t][j][1]);
            *reinterpret_cast<float2*>(p1) = make_float2(acc[t][j][2], acc[t][j][3]);
        }
    }
}

// ---------------- reduce + L2 normalize ----------------
__global__ void __launch_bounds__(320) reduce_norm_kernel(float* __restrict__ out) {
    const int row = blockIdx.x;
    const int d = threadIdx.x;
    __shared__ float ssum[10];
    __shared__ float sinv;
    float a = 0.0f;
    if (d < DDIM) {
#pragma unroll
        for (int s = 0; s < NSPLIT; s++)
            a += g_partial[((size_t)s * BDIM + row) * NPAD_OUT + d];
    }
    float sq = a * a;
#pragma unroll
    for (int off = 16; off > 0; off >>= 1)
        sq += __shfl_xor_sync(0xFFFFFFFFu, sq, off);
    if ((threadIdx.x & 31) == 0) ssum[threadIdx.x >> 5] = sq;
    __syncthreads();
    if (threadIdx.x == 0) {
        float t = 0.0f;
#pragma unroll
        for (int i = 0; i < 10; i++) t += ssum[i];
        sinv = 1.0f / (sqrtf(t) + 1e-7f);
    }
    __syncthreads();
    if (d < DDIM)
        out[(size_t)row * DDIM + d] = a * sinv;
}

// ---------------- launch ----------------
extern "C" void kernel_launch(void* const* d_in, const int* in_sizes, int n_in,
                              void* d_out, int out_size) {
    const float* labels = (const float*)d_in[0];
    const float* weight = (const float*)d_in[1];
    if (n_in >= 2 && in_sizes[0] == VDIM * DDIM) {   // defensive: identify by size
        labels = (const float*)d_in[1];
        weight = (const float*)d_in[0];
    }
    float* out = (float*)d_out;

    gemm_kernel<<<dim3(BDIM / MTILE, 2, NSPLIT), 256>>>(labels, weight);
    reduce_norm_kernel<<<BDIM, 320>>>(out);
}